// round 17
// baseline (speedup 1.0000x reference)
#include <cuda_runtime.h>
#include <math.h>

#define TT 2048
#define DD 1024
#define KQ 32
#define NT 8192
#define KTOP 4

typedef unsigned long long ull;

// scratch
__device__ float g_P[4][NT * 64];            // proj partials (k-split 4)
__device__ float g_Qf[NT * KQ];              // reduced Q [row][k]
__device__ float g_Kf[NT * KQ];              // reduced K [row][k]
__device__ float g_cv[NT * 16];              // candidate values [row][quarter][4]
__device__ __align__(16) int g_ci[NT * 16];  // candidate indices

// ---- packed f32x2 helpers ---------------------------------------------------
__device__ __forceinline__ void unpack2(ull v, float& lo, float& hi) {
    asm("mov.b64 {%0, %1}, %2;" : "=f"(lo), "=f"(hi) : "l"(v));
}
__device__ __forceinline__ ull ffma2(ull a, ull b, ull c) {
    ull d;
    asm("fma.rn.f32x2 %0, %1, %2, %3;" : "=l"(d) : "l"(a), "l"(b), "l"(c));
    return d;
}

// sorted top-4 insert (v0>=v1>=v2>=v3)
__device__ __forceinline__ void upd4(float* v, int* ix, float s, int si) {
    if (s > v[3]) {
        if (s > v[1]) {
            v[3] = v[2]; ix[3] = ix[2]; v[2] = v[1]; ix[2] = ix[1];
            if (s > v[0]) { v[1] = v[0]; ix[1] = ix[0]; v[0] = s; ix[0] = si; }
            else          { v[1] = s; ix[1] = si; }
        } else {
            if (s > v[2]) { v[3] = v[2]; ix[3] = ix[2]; v[2] = s; ix[2] = si; }
            else          { v[3] = s; ix[3] = si; }
        }
    }
}

// ---------------------------------------------------------------------------
// Kernel 1 (R16): projection partials, register-prefetched. grid = 512, 256 thr.
// ---------------------------------------------------------------------------
__global__ __launch_bounds__(256) void proj_kernel(
    const float* __restrict__ x, const float* __restrict__ Wq,
    const float* __restrict__ Wk)
{
    __shared__ __align__(16) float Xd[32][132];  // [k][2*row] duplicated pairs
    __shared__ __align__(16) float Wt[32][68];   // [k][col]

    const int tid  = threadIdx.x;
    const int row0 = (blockIdx.x >> 2) * 64;
    const int kh   = blockIdx.x & 3;
    const int rg   = tid >> 4;      // 0..15
    const int tc   = tid & 15;      // cols 4tc..4tc+3
    const int r0   = rg * 4;

    const int lrow = tid >> 3;
    const int lk4  = (tid & 7) * 4;
    const float* xrowA = &x[(size_t)(row0 + lrow) * DD];
    const float* xrowB = &x[(size_t)(row0 + lrow + 32) * DD];
    const float* WrA = (lrow < KQ) ? &Wq[lrow * DD] : &Wk[(lrow - KQ) * DD];
    const float* WrB = &Wk[(lrow + 32 - KQ) * DD];

    float4 px0, px1, pw0, pw1;
    auto ldg = [&](int kt) {
        const int kb = kh * 256 + kt * 32 + lk4;
        px0 = *(const float4*)&xrowA[kb];
        px1 = *(const float4*)&xrowB[kb];
        pw0 = *(const float4*)&WrA[kb];
        pw1 = *(const float4*)&WrB[kb];
    };
    auto sts = [&]() {
        const float* xv0 = (const float*)&px0;
        const float* xv1 = (const float*)&px1;
        const float* wv0 = (const float*)&pw0;
        const float* wv1 = (const float*)&pw1;
        #pragma unroll
        for (int i = 0; i < 4; i++) {
            *(float2*)&Xd[lk4 + i][2 * lrow]        = make_float2(xv0[i], xv0[i]);
            *(float2*)&Xd[lk4 + i][2 * (lrow + 32)] = make_float2(xv1[i], xv1[i]);
            Wt[lk4 + i][lrow]      = wv0[i];
            Wt[lk4 + i][lrow + 32] = wv1[i];
        }
    };

    ull acc[4][2];
    #pragma unroll
    for (int i = 0; i < 4; i++) { acc[i][0] = 0ULL; acc[i][1] = 0ULL; }

    ldg(0); sts();
    __syncthreads();

    for (int kt = 0; kt < 8; kt++) {
        if (kt < 7) ldg(kt + 1);
        #pragma unroll
        for (int k = 0; k < 32; k++) {
            ulonglong2 xa = *(const ulonglong2*)&Xd[k][2 * r0];
            ulonglong2 xb = *(const ulonglong2*)&Xd[k][2 * r0 + 4];
            ulonglong2 wp = *(const ulonglong2*)&Wt[k][4 * tc];
            ull xr[4] = { xa.x, xa.y, xb.x, xb.y };
            #pragma unroll
            for (int i = 0; i < 4; i++) {
                acc[i][0] = ffma2(xr[i], wp.x, acc[i][0]);
                acc[i][1] = ffma2(xr[i], wp.y, acc[i][1]);
            }
        }
        __syncthreads();
        if (kt < 7) {
            sts();
            __syncthreads();
        }
    }

    #pragma unroll
    for (int i = 0; i < 4; i++) {
        size_t r = (size_t)(row0 + r0 + i) * 64;
        float l0, h0, l1, h1;
        unpack2(acc[i][0], l0, h0);
        unpack2(acc[i][1], l1, h1);
        *(float4*)&g_P[kh][r + 4 * tc] = make_float4(l0, h0, l1, h1);
    }
}

// ---------------------------------------------------------------------------
// Kernel 2 (R16): reduce partials + bias; emit Q and K [row][k].
// ---------------------------------------------------------------------------
__global__ __launch_bounds__(256) void reduce_kernel(
    const float* __restrict__ bq, const float* __restrict__ bk)
{
    const int tid  = threadIdx.x;
    const int row0 = blockIdx.x * 64;

    #pragma unroll
    for (int l = 0; l < 4; l++) {
        int f = tid + l * 256;
        int row = f >> 4, c4 = f & 15;
        size_t base = (size_t)(row0 + row) * 64 + c4 * 4;
        float4 a = *(const float4*)&g_P[0][base];
        float4 p1 = *(const float4*)&g_P[1][base];
        float4 p2 = *(const float4*)&g_P[2][base];
        float4 p3 = *(const float4*)&g_P[3][base];
        float4 s;
        s.x = ((a.x + p1.x) + p2.x) + p3.x;
        s.y = ((a.y + p1.y) + p2.y) + p3.y;
        s.z = ((a.z + p1.z) + p2.z) + p3.z;
        s.w = ((a.w + p1.w) + p2.w) + p3.w;
        if (c4 < 8) {
            int c = c4 * 4;
            s.x += bq[c]; s.y += bq[c + 1]; s.z += bq[c + 2]; s.w += bq[c + 3];
            *(float4*)&g_Qf[(size_t)(row0 + row) * KQ + c] = s;
        } else {
            int c = c4 * 4 - 32;
            s.x += bk[c]; s.y += bk[c + 1]; s.z += bk[c + 2]; s.w += bk[c + 3];
            *(float4*)&g_Kf[(size_t)(row0 + row) * KQ + c] = s;
        }
    }
}

// ---------------------------------------------------------------------------
// Kernel 3: FFMA2 sim, key-split x4. grid = 512 (128 row-tiles x 4 quarters),
// 256 thr. Block: 64 rows x 512 keys (4 tiles of 128). Thread: 4 rows x 8 keys.
// ---------------------------------------------------------------------------
__global__ __launch_bounds__(256) void sim_topk()
{
    __shared__ __align__(16) float Qd[32][132];   // [k][2*row], 64 rows
    __shared__ __align__(16) float Kt[32][132];   // [k][key], 128 keys

    const int tid   = threadIdx.x;
    const int row0  = (blockIdx.x >> 2) * 64;
    const int kq4   = blockIdx.x & 3;      // key quarter
    const int b     = row0 >> 11;
    const int rg    = tid >> 4;     // 0..15 -> rows r0..r0+3
    const int cg    = tid & 15;     // keys 4cg..4cg+3, 4cg+64..4cg+67
    const int r0    = rg * 4;

    // stage Q (64 rows x 32 k) duplicated pairs
    #pragma unroll
    for (int l = 0; l < 2; l++) {
        int f = tid + l * 256;
        int row = f >> 3, kc = f & 7;
        float4 v = *(const float4*)&g_Qf[(size_t)(row0 + row) * KQ + kc * 4];
        *(float2*)&Qd[kc * 4 + 0][2 * row] = make_float2(v.x, v.x);
        *(float2*)&Qd[kc * 4 + 1][2 * row] = make_float2(v.y, v.y);
        *(float2*)&Qd[kc * 4 + 2][2 * row] = make_float2(v.z, v.z);
        *(float2*)&Qd[kc * 4 + 3][2 * row] = make_float2(v.w, v.w);
    }

    const float* Kb = &g_Kf[((size_t)b * TT + kq4 * 512) * KQ];
    const int skey = tid >> 3;          // key (l adds 32)
    const int skc  = (tid & 7) * 4;     // k offset
    float4 pr[4];
    auto ldg = [&](int t) {
        const int kbase = t * 128;
        #pragma unroll
        for (int l = 0; l < 4; l++)
            pr[l] = *(const float4*)&Kb[(size_t)(kbase + skey + l * 32) * KQ + skc];
    };
    auto sts = [&]() {
        #pragma unroll
        for (int l = 0; l < 4; l++) {
            const int key = skey + l * 32;
            Kt[skc + 0][key] = pr[l].x;
            Kt[skc + 1][key] = pr[l].y;
            Kt[skc + 2][key] = pr[l].z;
            Kt[skc + 3][key] = pr[l].w;
        }
    };

    float tv[4][4]; int ti[4][4];
    #pragma unroll
    for (int i = 0; i < 4; i++)
        #pragma unroll
        for (int p = 0; p < 4; p++) { tv[i][p] = -INFINITY; ti[i][p] = 0; }

    ldg(0); sts();
    __syncthreads();

    for (int t = 0; t < 4; t++) {
        if (t < 3) ldg(t + 1);

        ull acc[4][4];
        #pragma unroll
        for (int i = 0; i < 4; i++)
            #pragma unroll
            for (int j = 0; j < 4; j++) acc[i][j] = 0ULL;

        #pragma unroll
        for (int k = 0; k < 32; k++) {
            ulonglong2 qa = *(const ulonglong2*)&Qd[k][2 * r0];
            ulonglong2 qb = *(const ulonglong2*)&Qd[k][2 * r0 + 4];
            ulonglong2 k01 = *(const ulonglong2*)&Kt[k][4 * cg];
            ulonglong2 k23 = *(const ulonglong2*)&Kt[k][4 * cg + 64];
            ull qr[4] = { qa.x, qa.y, qb.x, qb.y };
            #pragma unroll
            for (int i = 0; i < 4; i++) {
                acc[i][0] = ffma2(qr[i], k01.x, acc[i][0]);
                acc[i][1] = ffma2(qr[i], k01.y, acc[i][1]);
                acc[i][2] = ffma2(qr[i], k23.x, acc[i][2]);
                acc[i][3] = ffma2(qr[i], k23.y, acc[i][3]);
            }
        }

        // prefiltered top-4 update
        const int ib = kq4 * 512 + t * 128 + 4 * cg;
        #pragma unroll
        for (int i = 0; i < 4; i++) {
            float v[8];
            unpack2(acc[i][0], v[0], v[1]);
            unpack2(acc[i][1], v[2], v[3]);
            unpack2(acc[i][2], v[4], v[5]);
            unpack2(acc[i][3], v[6], v[7]);
            float m = fmaxf(fmaxf(fmaxf(v[0], v[1]), fmaxf(v[2], v[3])),
                            fmaxf(fmaxf(v[4], v[5]), fmaxf(v[6], v[7])));
            if (m > tv[i][3]) {
                upd4(tv[i], ti[i], v[0], ib);
                upd4(tv[i], ti[i], v[1], ib + 1);
                upd4(tv[i], ti[i], v[2], ib + 2);
                upd4(tv[i], ti[i], v[3], ib + 3);
                upd4(tv[i], ti[i], v[4], ib + 64);
                upd4(tv[i], ti[i], v[5], ib + 65);
                upd4(tv[i], ti[i], v[6], ib + 66);
                upd4(tv[i], ti[i], v[7], ib + 67);
            }
        }

        __syncthreads();
        if (t < 3) {
            sts();
            __syncthreads();
        }
    }

    // 16-lane shuffle merge (snapshot then insert; xor 1,2,4,8 within cg group)
    #pragma unroll
    for (int off = 1; off <= 8; off <<= 1) {
        #pragma unroll
        for (int i = 0; i < 4; i++) {
            float ov[4]; int oi[4];
            #pragma unroll
            for (int p = 0; p < 4; p++) {
                ov[p] = __shfl_xor_sync(0xFFFFFFFFu, tv[i][p], off);
                oi[p] = __shfl_xor_sync(0xFFFFFFFFu, ti[i][p], off);
            }
            #pragma unroll
            for (int p = 0; p < 4; p++)
                upd4(tv[i], ti[i], ov[p], oi[p]);
        }
    }

    if (cg == 0) {
        #pragma unroll
        for (int i = 0; i < 4; i++) {
            size_t base = (size_t)(row0 + r0 + i) * 16 + kq4 * 4;
            *(float4*)&g_cv[base] = make_float4(tv[i][0], tv[i][1], tv[i][2], tv[i][3]);
            *(int4*)&g_ci[base]   = make_int4(ti[i][0], ti[i][1], ti[i][2], ti[i][3]);
        }
    }
}

// ---------------------------------------------------------------------------
// Kernel 4: merge 16 candidates + gather + mean. Warp per row, grid = 1024.
// ---------------------------------------------------------------------------
__global__ __launch_bounds__(256) void gather_kernel(
    const float* __restrict__ x, float* __restrict__ out)
{
    const int tid  = threadIdx.x;
    const int wid  = tid >> 5;
    const int lane = tid & 31;
    const int row  = blockIdx.x * 8 + wid;
    const int b    = row >> 11;

    float cv[16]; int ci[16];
    #pragma unroll
    for (int q = 0; q < 4; q++) {
        float4 a = *(const float4*)&g_cv[(size_t)row * 16 + q * 4];
        int4  ia = *(const int4*)&g_ci[(size_t)row * 16 + q * 4];
        cv[q * 4 + 0] = a.x; cv[q * 4 + 1] = a.y;
        cv[q * 4 + 2] = a.z; cv[q * 4 + 3] = a.w;
        ci[q * 4 + 0] = ia.x; ci[q * 4 + 1] = ia.y;
        ci[q * 4 + 2] = ia.z; ci[q * 4 + 3] = ia.w;
    }
    int sel[4];
    #pragma unroll
    for (int p = 0; p < KTOP; p++) {
        int best = 0;
        #pragma unroll
        for (int k = 1; k < 16; k++)
            if (cv[k] > cv[best]) best = k;
        sel[p] = ci[best];
        cv[best] = -INFINITY;
    }

    const float4* xb4 = (const float4*)(x + (size_t)b * TT * DD);
    const float4* n0 = xb4 + (size_t)sel[0] * 256;
    const float4* n1 = xb4 + (size_t)sel[1] * 256;
    const float4* n2 = xb4 + (size_t)sel[2] * 256;
    const float4* n3 = xb4 + (size_t)sel[3] * 256;
    float4* o4 = (float4*)out + (size_t)row * 256;

    #pragma unroll
    for (int j = 0; j < 8; j++) {
        int c = lane + j * 32;
        float4 A = n0[c], B = n1[c], C = n2[c], D = n3[c];
        float4 o;
        o.x = (A.x + B.x + C.x + D.x) * 0.25f;
        o.y = (A.y + B.y + C.y + D.y) * 0.25f;
        o.z = (A.z + B.z + C.z + D.z) * 0.25f;
        o.w = (A.w + B.w + C.w + D.w) * 0.25f;
        o4[c] = o;
    }
}

// ---------------------------------------------------------------------------
extern "C" void kernel_launch(void* const* d_in, const int* in_sizes, int n_in,
                              void* d_out, int out_size)
{
    const float* x  = (const float*)d_in[0];
    const float* Wq = (const float*)d_in[1];
    const float* bq = (const float*)d_in[2];
    const float* Wk = (const float*)d_in[3];
    const float* bk = (const float*)d_in[4];
    float* out = (float*)d_out;

    proj_kernel<<<512, 256>>>(x, Wq, Wk);
    reduce_kernel<<<128, 256>>>(bq, bk);
    sim_topk<<<512, 256>>>();
    gather_kernel<<<1024, 256>>>(x, out);
}